// round 7
// baseline (speedup 1.0000x reference)
#include <cuda_runtime.h>
#include <cuda_bf16.h>

// TimeWarp, persistent-block pipelined kernel.
//   1184 blocks (148 SM x 8) grid-stride over 4096 tiles (b, i-group, j-tile).
//   Per tile: cp.async-prefetched raw (v0,v1) pairs -> smem lerp -> P-tile -> stream stores.
//   Tile k+1's gathers are in flight (LDGSTS) while tile k streams: setup latency hidden.
//   sP rows padded to 33 floats -> conflict-free LDS in the hot loop.
// B=32, F=128, T=8192, fp32.

#define NB 32
#define NF 128
#define NT 8192
#define TILE_J   256
#define TILE_C   (TILE_J / 4)      // 64 chunks
#define TILE_I   32
#define MAX_ROWS 12                // y-span over 256 j's <= ~4.1 -> <=8 rows needed; 12 safe
#define PSTR     33                // padded sP row stride (kills bank conflicts)
#define NTILES   4096              // 32 b * 4 ig * 32 jt
#define NBLOCKS  1184              // 148 SMs * 8 blocks

#define CP_ASYNC4(dst, src) \
    asm volatile("cp.async.ca.shared.global [%0], [%1], 4;\n" :: "r"(dst), "l"(src))
#define CP_COMMIT()  asm volatile("cp.async.commit_group;\n" ::: "memory")
#define CP_WAIT1()   asm volatile("cp.async.wait_group 1;\n" ::: "memory")

__global__ __launch_bounds__(256, 8)
void timewarp_pers(const float* __restrict__ S,
                   const int*   __restrict__ psrc,
                   const int*   __restrict__ pdst,
                   float*       __restrict__ out)
{
    __shared__ float  sRaw[2][MAX_ROWS * TILE_I * 2];  // (v0,v1) pairs, 3KB per buf
    __shared__ float  sP  [2][MAX_ROWS * PSTR];        // x-resampled rows, padded stride
    __shared__ float4 sWy4[2][TILE_C];
    __shared__ int    sYc [2][TILE_C];

    const int t = threadIdx.x;

    const float s = (float)__ldg(psrc);
    const float d = (float)__ldg(pdst);
    const float rl = s / d;
    const float rr = ((float)NT - s) / ((float)NT - d);

    // y(j) per the reference (monotone nondecreasing)
    auto yval = [&](float tf) -> float {
        float idx = (tf < d) ? (tf * rl) : fmaf(tf - d, rr, s);
        idx = fminf(fmaxf(idx, 0.0f), (float)(NT - 1));
        float y = idx * (1.0f / (float)(NT - 1)) * (float)(NF - 1);
        return fminf(fmaxf(y, 0.0f), (float)(NF - 1));
    };

    // Issue cp.async gathers for one tile's raw rows into sRaw[buf]. No commit here.
    auto issue_prefetch = [&](int tile, int buf) {
        const int b  = tile >> 7;
        const int ig = (tile >> 5) & 3;
        const int jt = tile & 31;
        const int j_base = jt << 8;
        const int Ymin = (int)floorf(yval((float)j_base));
        int nrows = (int)floorf(yval((float)(j_base + TILE_J - 1))) + 3 - Ymin;
        if (nrows > MAX_ROWS) nrows = MAX_ROWS;

        const float* Sb = S + ((size_t)b * NF) * (size_t)NT;
        for (int v = t; v < nrows * TILE_I; v += 256) {
            const int r  = v >> 5;
            const int il = v & (TILE_I - 1);
            const int i  = (ig << 5) + il;
            const int rs = min(Ymin + r, NF - 1);      // border clamp / pad rows

            float x_pix = ((float)i / (float)(NF - 1)) * (float)(NT - 1);
            x_pix = fminf(fmaxf(x_pix, 0.0f), (float)(NT - 1));
            const int x0 = (int)floorf(x_pix);
            const int x1 = min(x0 + 1, NT - 1);

            const float* row = Sb + (size_t)rs * NT;
            unsigned dst = (unsigned)__cvta_generic_to_shared(&sRaw[buf][v * 2]);
            CP_ASYNC4(dst,     row + x0);
            CP_ASYNC4(dst + 4, row + x1);
        }
    };

    // ---- prologue: prefetch first tile ----
    issue_prefetch(blockIdx.x, 0);
    CP_COMMIT();

    int buf = 0;
    for (int tile = blockIdx.x; tile < NTILES; tile += NBLOCKS) {
        // prefetch next tile into the other buffer (empty group keeps wait-count right)
        const int nxt = tile + NBLOCKS;
        if (nxt < NTILES) issue_prefetch(nxt, buf ^ 1);
        CP_COMMIT();
        CP_WAIT1();                                   // current tile's raw data resident
        __syncthreads();

        const int b  = tile >> 7;
        const int ig = (tile >> 5) & 3;
        const int jt = tile & 31;
        const int j_base = jt << 8;
        const int i_base = ig << 5;
        const int Ymin = (int)floorf(yval((float)j_base));
        int nrows = (int)floorf(yval((float)(j_base + TILE_J - 1))) + 3 - Ymin;
        if (nrows > MAX_ROWS) nrows = MAX_ROWS;

        // ---- per-j tables ----
        {
            float y  = yval((float)(j_base + t));
            float yf = floorf(y);
            ((float*)sWy4[buf])[t] = y - yf;
            if ((t & 3) == 0) sYc[buf][t >> 2] = (int)yf;
        }

        // ---- raw -> P (x-lerp), into padded rows ----
        for (int v = t; v < nrows * TILE_I; v += 256) {
            const int r  = v >> 5;
            const int il = v & (TILE_I - 1);
            const int i  = i_base + il;

            float x_pix = ((float)i / (float)(NF - 1)) * (float)(NT - 1);
            x_pix = fminf(fmaxf(x_pix, 0.0f), (float)(NT - 1));
            const float wx = x_pix - floorf(x_pix);

            const float v0 = sRaw[buf][v * 2];
            const float v1 = sRaw[buf][v * 2 + 1];
            sP[buf][r * PSTR + il] = fmaf(wx, v1 - v0, v0);
        }
        __syncthreads();

        // ---- stream TILE_I rows x 256 j ----
        const int tx = t & (TILE_C - 1);
        const int ty = t >> 6;                        // 0..3

        const float4 wy = sWy4[buf][tx];
        const int    rel = sYc[buf][tx] - Ymin;       // 0..nrows-3
        const float* pc  = sP[buf] + rel * PSTR;

        const bool s1 = wy.y < wy.x;
        const bool s2 = wy.z < wy.x;
        const bool s3 = wy.w < wy.x;

        float* obase = out + ((size_t)b * NF + i_base) * (size_t)NT
                           + (size_t)(j_base + tx * 4);

#pragma unroll
        for (int r = 0; r < TILE_I / 4; r++) {        // 8 iterations
            const int il = r * 4 + ty;

            const float pA = pc[il];
            const float pB = pc[PSTR + il];
            const float pC = pc[2 * PSTR + il];

            float o0 = fmaf(wy.x, pB - pA, pA);
            float l1 = s1 ? pB : pA, h1 = s1 ? pC : pB;
            float l2 = s2 ? pB : pA, h2 = s2 ? pC : pB;
            float l3 = s3 ? pB : pA, h3 = s3 ? pC : pB;
            float o1 = fmaf(wy.y, h1 - l1, l1);
            float o2 = fmaf(wy.z, h2 - l2, l2);
            float o3 = fmaf(wy.w, h3 - l3, l3);

            __stcs(reinterpret_cast<float4*>(obase + (size_t)il * NT),
                   make_float4(o0, o1, o2, o3));
        }

        buf ^= 1;
    }
}

extern "C" void kernel_launch(void* const* d_in, const int* in_sizes, int n_in,
                              void* d_out, int out_size)
{
    const float* S    = (const float*)d_in[0];
    const int*   psrc = (const int*)d_in[1];
    const int*   pdst = (const int*)d_in[2];
    float*       out  = (float*)d_out;

    timewarp_pers<<<NBLOCKS, 256>>>(S, psrc, pdst, out);
}

// round 8
// speedup vs baseline: 1.0308x; 1.0308x over previous
#include <cuda_runtime.h>
#include <cuda_bf16.h>

// TimeWarp, contiguous-stream version.
//  Prep (tiny): per-chunk tables g_wy4[2048] (frac y for 4 j's) and g_yf[2048] (floor y).
//  Main: block = (b, pair of freq rows i0,i1). Setup = x-lerp column sP[2][132] (264 gathers).
//        Stream = 8 iterations, each writing 1KB sequentially into each of the two
//        contiguous 32KB output rows. One long write run per row -> HBM row-buffer friendly.
// B=32, F=128, T=8192, fp32.

#define NB 32
#define NF 128
#define NT 8192
#define NCH (NT / 4)              // 2048 chunks of 4 j's

__device__ __align__(16) float4 g_wy4[NCH];
__device__ __align__(16) int    g_yf[NCH];

// ---------------- prep: per-chunk y tables (2048 threads total) ----------------
__global__ __launch_bounds__(256)
void prep_tables(const int* __restrict__ psrc, const int* __restrict__ pdst)
{
    const int c = blockIdx.x * blockDim.x + threadIdx.x;   // chunk id
    if (c >= NCH) return;

    const float s = (float)__ldg(psrc);
    const float d = (float)__ldg(pdst);
    const float rl = s / d;
    const float rr = ((float)NT - s) / ((float)NT - d);

    float w[4]; int yf0 = 0;
#pragma unroll
    for (int k = 0; k < 4; k++) {
        float tf  = (float)(c * 4 + k);
        float idx = (tf < d) ? (tf * rl) : fmaf(tf - d, rr, s);
        idx = fminf(fmaxf(idx, 0.0f), (float)(NT - 1));
        float y = idx * (1.0f / (float)(NT - 1)) * (float)(NF - 1);
        y = fminf(fmaxf(y, 0.0f), (float)(NF - 1));
        float yf = floorf(y);
        w[k] = y - yf;
        if (k == 0) yf0 = (int)yf;
    }
    g_wy4[c] = make_float4(w[0], w[1], w[2], w[3]);
    g_yf[c]  = yf0;
}

// ---------------- main: contiguous row streams ----------------
__global__ __launch_bounds__(256, 8)
void timewarp_rows(const float* __restrict__ S, float* __restrict__ out)
{
    __shared__ float sP[2][132];             // x-lerped column per i; rows 128..131 pad row 127

    const int t  = threadIdx.x;              // 256 threads
    const int ih = blockIdx.x;               // 0..63  i-pair
    const int b  = blockIdx.y;               // 0..31  batch

    // ---- setup: x-resample the two columns (264 work items) ----
    const float* Sb = S + (size_t)b * (size_t)(NF * NT);
    for (int v = t; v < 2 * 132; v += 256) {
        const int ii = v & 1;
        const int r  = v >> 1;
        const int rs = min(r, NF - 1);
        const int i  = ih * 2 + ii;

        float x_pix = ((float)i / (float)(NF - 1)) * (float)(NT - 1);
        x_pix = fminf(fmaxf(x_pix, 0.0f), (float)(NT - 1));
        const float x0f = floorf(x_pix);
        const int   x0  = (int)x0f;
        const int   x1  = min(x0 + 1, NT - 1);
        const float wx  = x_pix - x0f;

        const float* row = Sb + (size_t)rs * NT;
        const float v0 = __ldg(row + x0);
        const float v1 = __ldg(row + x1);
        sP[ii][r] = fmaf(wx, v1 - v0, v0);
    }
    __syncthreads();

    // ---- stream: 8 iterations x 256 chunks, sequential through both 32KB rows ----
    const int i0 = ih * 2;
    float* o0 = out + ((size_t)b * NF + i0) * (size_t)NT;
    float* o1 = o0 + NT;

#pragma unroll
    for (int it = 0; it < 8; it++) {
        const int c = it * 256 + t;          // chunk id: block walks rows front-to-back

        const float4 wy = __ldg(&g_wy4[c]);  // L1-resident after first pass
        const int    Y  = __ldg(&g_yf[c]);

        const bool s1 = wy.y < wy.x;         // floor advanced within chunk
        const bool s2 = wy.z < wy.x;
        const bool s3 = wy.w < wy.x;

#pragma unroll
        for (int ii = 0; ii < 2; ii++) {
            const float pA = sP[ii][Y];
            const float pB = sP[ii][Y + 1];
            const float pC = sP[ii][Y + 2];

            float o0v = fmaf(wy.x, pB - pA, pA);
            float l1 = s1 ? pB : pA, h1 = s1 ? pC : pB;
            float l2 = s2 ? pB : pA, h2 = s2 ? pC : pB;
            float l3 = s3 ? pB : pA, h3 = s3 ? pC : pB;
            float o1v = fmaf(wy.y, h1 - l1, l1);
            float o2v = fmaf(wy.z, h2 - l2, l2);
            float o3v = fmaf(wy.w, h3 - l3, l3);

            __stcs(reinterpret_cast<float4*>((ii ? o1 : o0) + (size_t)c * 4),
                   make_float4(o0v, o1v, o2v, o3v));
        }
    }
}

extern "C" void kernel_launch(void* const* d_in, const int* in_sizes, int n_in,
                              void* d_out, int out_size)
{
    const float* S    = (const float*)d_in[0];
    const int*   psrc = (const int*)d_in[1];
    const int*   pdst = (const int*)d_in[2];
    float*       out  = (float*)d_out;

    prep_tables<<<(NCH + 255) / 256, 256>>>(psrc, pdst);

    dim3 grid(NF / 2, NB);                   // 64 x 32 = 2048 blocks
    timewarp_rows<<<grid, 256>>>(S, out);
}

// round 9
// speedup vs baseline: 1.0497x; 1.0183x over previous
#include <cuda_runtime.h>
#include <cuda_bf16.h>

// TimeWarp, single fused kernel (R6 structure, default write-back stores).
// Block = (b, j-tile of 256, i-group of 32 freq rows) -> grid 4096.
//   Setup:  wy[256], per-chunk Y[64], x-resampled P-tile (<=12 rows x 32 i's) in smem.
//   Stream: out[b,i,j] = lerp_y over smem P-tile; coalesced STG.128 (write-back).
// B=32, F=128, T=8192, fp32.

#define NB 32
#define NF 128
#define NT 8192
#define TILE_J   256              // j's per block
#define TILE_C   (TILE_J / 4)     // 64 float4-chunks per block
#define TILE_I   32               // freq rows per block
#define MAX_ROWS 12               // y-span over 256 j's <= ~4.1 (+2 lerp +1) -> <=8; 12 safe

__global__ __launch_bounds__(256, 8)
void timewarp_fused(const float* __restrict__ S,
                    const int*   __restrict__ psrc,
                    const int*   __restrict__ pdst,
                    float*       __restrict__ out)
{
    __shared__ float  sP[MAX_ROWS * TILE_I];   // x-resampled rows [Ymin..), i-slice only
    __shared__ float4 sWy4[TILE_C];            // frac(y) per j, float4 per chunk
    __shared__ int    sYc[TILE_C];             // floor(y) at each chunk's first j

    const int t  = threadIdx.x;                // 256 threads
    const int jt = blockIdx.x & 31;            // 0..31  j-tile
    const int ig = blockIdx.x >> 5;            // 0..3   i-group
    const int b  = blockIdx.y;                 // 0..31  batch
    const int j_base = jt * TILE_J;
    const int i_base = ig * TILE_I;

    // ---------- Phase 1a: per-j tables ----------
    {
        const float s = (float)__ldg(psrc);
        const float d = (float)__ldg(pdst);
        const float rl = s / d;
        const float rr = ((float)NT - s) / ((float)NT - d);

        float tf  = (float)(j_base + t);
        float idx = (tf < d) ? (tf * rl) : fmaf(tf - d, rr, s);
        idx = fminf(fmaxf(idx, 0.0f), (float)(NT - 1));
        float y = idx * (1.0f / (float)(NT - 1)) * (float)(NF - 1);
        y = fminf(fmaxf(y, 0.0f), (float)(NF - 1));
        float yf = floorf(y);
        ((float*)sWy4)[t] = y - yf;
        if ((t & 3) == 0) sYc[t >> 2] = (int)yf;
    }
    __syncthreads();

    // ---------- Phase 1b: build P-tile (x-resample needed rows, this i-slice) ----------
    const int Ymin  = sYc[0];                        // y(j) monotone nondecreasing
    int nrows = sYc[TILE_C - 1] + 2 - Ymin + 1;      // cover Y..Y+2 of last chunk
    if (nrows > MAX_ROWS) nrows = MAX_ROWS;

    const float* Sb = S + (size_t)b * (size_t)(NF * NT);
    for (int v = t; v < nrows * TILE_I; v += 256) {
        const int r  = v / TILE_I;
        const int il = v & (TILE_I - 1);
        const int i  = i_base + il;
        const int rs = min(Ymin + r, NF - 1);        // border clamp / pad rows

        float x_pix = ((float)i / (float)(NF - 1)) * (float)(NT - 1);
        x_pix = fminf(fmaxf(x_pix, 0.0f), (float)(NT - 1));
        const float x0f = floorf(x_pix);
        const int   x0  = (int)x0f;
        const int   x1  = min(x0 + 1, NT - 1);
        const float wx  = x_pix - x0f;

        const float* row = Sb + (size_t)rs * NT;
        const float v0 = __ldg(row + x0);
        const float v1 = __ldg(row + x1);
        sP[v] = fmaf(wx, v1 - v0, v0);
    }
    __syncthreads();

    // ---------- Phase 2: stream TILE_I freq rows x 256 j ----------
    const int tx = t & (TILE_C - 1);                 // chunk within tile (warp-contiguous)
    const int ty = t >> 6;                           // i-offset 0..3

    const float4 wy = sWy4[tx];
    const int    rel = sYc[tx] - Ymin;               // 0..nrows-3
    const float* pc  = sP + rel * TILE_I;

    const bool s1 = wy.y < wy.x;
    const bool s2 = wy.z < wy.x;
    const bool s3 = wy.w < wy.x;

    float* obase = out + ((size_t)b * NF + i_base) * (size_t)NT + (size_t)(j_base + tx * 4);

#pragma unroll
    for (int r = 0; r < TILE_I / 4; r++) {           // 8 iterations
        const int il = r * 4 + ty;

        const float pA = pc[il];
        const float pB = pc[TILE_I + il];
        const float pC = pc[2 * TILE_I + il];

        float o0 = fmaf(wy.x, pB - pA, pA);
        float l1 = s1 ? pB : pA, h1 = s1 ? pC : pB;
        float l2 = s2 ? pB : pA, h2 = s2 ? pC : pB;
        float l3 = s3 ? pB : pA, h3 = s3 ? pC : pB;
        float o1 = fmaf(wy.y, h1 - l1, l1);
        float o2 = fmaf(wy.z, h2 - l2, l2);
        float o3 = fmaf(wy.w, h3 - l3, l3);

        // default write-back store (A/B vs __stcs of all prior rounds)
        *reinterpret_cast<float4*>(obase + (size_t)il * NT) =
            make_float4(o0, o1, o2, o3);
    }
}

extern "C" void kernel_launch(void* const* d_in, const int* in_sizes, int n_in,
                              void* d_out, int out_size)
{
    const float* S    = (const float*)d_in[0];
    const int*   psrc = (const int*)d_in[1];
    const int*   pdst = (const int*)d_in[2];
    float*       out  = (float*)d_out;

    dim3 grid((NT / TILE_J) * (NF / TILE_I), NB);    // (32*4) x 32 = 4096 blocks
    timewarp_fused<<<grid, 256>>>(S, psrc, pdst, out);
}